// round 17
// baseline (speedup 1.0000x reference)
#include <cuda_runtime.h>
#include <cuda_fp16.h>
#include <cstdint>

// out[8192,4096] = x[8192,4096] @ W[4096,4096] + bias[4096]  (fp32)
//
// fp16 1-product GEMM (C = Ah*Bh, fp32 accum) on mma.sync.
// R12: BK=64 (3-stage cp.async ring, 2 CTAs/SM) — halves barrier/stage count
// to amortize the ~400cyc/stage pipeline bubble measured at BK=32.

#define TOKENS 8192
#define SIZE_IN 4096
#define SIZE_OUT 4096

#define BM 128
#define BN 128
#define BK 64
#define NK64 (SIZE_IN / BK)        // 64 k-stages
#define NK32 (SIZE_IN / 32)        // 128 scratch blocks
#define THREADS 256
#define STAGES 3

// scratch: per (tile, ks32): 8KB fp16 tiles, linear; 64-k stage = 2 blocks = 16KB contiguous
#define ABLK_A 8192
#define ABLK_B 8192

// smem strides (16B multiples; conflict-free ldmatrix)
#define A_STRIDE 144               // 128B row + 16B pad (9 quad-banks)
#define B_STRIDE 272               // 256B row + 16B pad (17 quad-banks)
#define AS_PAD (128 * A_STRIDE)    // 18432
#define BS_PAD (64 * B_STRIDE)     // 17408
#define OFF_A 0
#define OFF_B AS_PAD
#define STAGE_BYTES (AS_PAD + BS_PAD)           // 35840
#define SMEM_TOTAL (STAGES * STAGE_BYTES)       // 107520 (x2 CTAs = 215040)

// ---------------- scratch ----------------
__device__ __align__(1024) unsigned char g_A[(size_t)(TOKENS / BM) * NK32 * ABLK_A];   // 64 MB
__device__ __align__(1024) unsigned char g_B[(size_t)(SIZE_OUT / BN) * NK32 * ABLK_B]; // 32 MB

// ---------------- helpers ----------------
__device__ __forceinline__ uint32_t smem_u32(const void* p) {
    uint32_t a;
    asm("{ .reg .u64 t; cvta.to.shared.u64 t, %1; cvt.u32.u64 %0, t; }" : "=r"(a) : "l"(p));
    return a;
}
__device__ __forceinline__ void cp16(uint32_t dst, const void* src) {
    asm volatile("cp.async.cg.shared.global [%0], [%1], 16;" :: "r"(dst), "l"(src));
}
__device__ __forceinline__ void cp_commit() {
    asm volatile("cp.async.commit_group;" ::: "memory");
}
template <int N> __device__ __forceinline__ void cp_wait() {
    asm volatile("cp.async.wait_group %0;" :: "n"(N) : "memory");
}
__device__ __forceinline__ void ldm_x4(uint32_t (&r)[4], uint32_t addr) {
    asm volatile("ldmatrix.sync.aligned.m8n8.x4.shared.b16 {%0,%1,%2,%3}, [%4];"
                 : "=r"(r[0]), "=r"(r[1]), "=r"(r[2]), "=r"(r[3]) : "r"(addr));
}
__device__ __forceinline__ void ldm_x4_t(uint32_t (&r)[4], uint32_t addr) {
    asm volatile("ldmatrix.sync.aligned.m8n8.x4.trans.shared.b16 {%0,%1,%2,%3}, [%4];"
                 : "=r"(r[0]), "=r"(r[1]), "=r"(r[2]), "=r"(r[3]) : "r"(addr));
}
__device__ __forceinline__ void mma_f16(float (&c)[4], const uint32_t (&a)[4],
                                        uint32_t b0, uint32_t b1) {
    asm("mma.sync.aligned.m16n8k16.row.col.f32.f16.f16.f32 "
        "{%0,%1,%2,%3}, {%4,%5,%6,%7}, {%8,%9}, {%0,%1,%2,%3};"
        : "+f"(c[0]), "+f"(c[1]), "+f"(c[2]), "+f"(c[3])
        : "r"(a[0]), "r"(a[1]), "r"(a[2]), "r"(a[3]), "r"(b0), "r"(b1));
}

// ---------------- prepass A: x[m][k] -> fp16 tiles ----------------
__global__ void conv_a_kernel(const float* __restrict__ x) {
    int g = blockIdx.x * blockDim.x + threadIdx.x;
    int m  = g >> 9;
    int k0 = (g & 511) << 3;
    const float4* s = reinterpret_cast<const float4*>(x + (size_t)m * SIZE_IN + k0);
    float4 v0 = s[0], v1 = s[1];
    union { __half2 h2[4]; uint4 u; } H;
    H.h2[0] = __floats2half2_rn(v0.x, v0.y);
    H.h2[1] = __floats2half2_rn(v0.z, v0.w);
    H.h2[2] = __floats2half2_rn(v1.x, v1.y);
    H.h2[3] = __floats2half2_rn(v1.z, v1.w);
    int mt = m >> 7, mr = m & 127, ks = k0 >> 5, kc = k0 & 31;
    size_t blk = (size_t)(mt * NK32 + ks) * ABLK_A;
    *reinterpret_cast<uint4*>(g_A + blk + mr * 64 + kc * 2) = H.u;
}

// ---------------- prepass B: W[k][n] -> fp16 tiles ----------------
__global__ void conv_b_kernel(const float* __restrict__ w) {
    int g = blockIdx.x * blockDim.x + threadIdx.x;
    int k  = g >> 9;
    int n0 = (g & 511) << 3;
    const float4* s = reinterpret_cast<const float4*>(w + (size_t)k * SIZE_OUT + n0);
    float4 v0 = s[0], v1 = s[1];
    union { __half2 h2[4]; uint4 u; } H;
    H.h2[0] = __floats2half2_rn(v0.x, v0.y);
    H.h2[1] = __floats2half2_rn(v0.z, v0.w);
    H.h2[2] = __floats2half2_rn(v1.x, v1.y);
    H.h2[3] = __floats2half2_rn(v1.z, v1.w);
    int nt = n0 >> 7, nc = n0 & 127, ks = k >> 5, kr = k & 31;
    size_t blk = (size_t)(nt * NK32 + ks) * ABLK_B;
    *reinterpret_cast<uint4*>(g_B + blk + kr * 256 + nc * 2) = H.u;
}

// ---------------- GEMM ----------------
__global__ __launch_bounds__(THREADS, 2)
void gemm_kernel(const float* __restrict__ bias, float* __restrict__ C) {
    extern __shared__ unsigned char smem[];

    const int tid  = threadIdx.x;
    const int lane = tid & 31;
    const int wid  = tid >> 5;
    const int wm   = wid & 3;    // 4 warps x 32 rows
    const int wn   = wid >> 2;   // 2 warps x 64 cols

    const int pid = blockIdx.x;
    const int NPG = 8 * (SIZE_OUT / BN);         // 256
    const int gid = pid / NPG;
    const int mt  = gid * 8 + (pid % NPG) % 8;
    const int nt  = (pid % NPG) / 8;

    const unsigned char* gAb = g_A + (size_t)mt * NK32 * ABLK_A;
    const unsigned char* gBb = g_B + (size_t)nt * NK32 * ABLK_B;
    const uint32_t sb0 = smem_u32(smem);

    // cp.async offsets per 64-k stage: A 1024 chunks, B 1024 chunks (4/thread each)
    // A: src block c>>9 (2 ks32 blocks), row (c>>2)&127, word c&3
    // B: src linear 16KB, row c>>4 (0..63), word c&15
    uint32_t adst[4], bdst[4];
#pragma unroll
    for (int i = 0; i < 4; i++) {
        int c = tid + i * 256;                    // 0..1023
        adst[i] = OFF_A + ((c >> 2) & 127) * A_STRIDE + (c >> 9) * 64 + (c & 3) * 16;
        bdst[i] = OFF_B + (c >> 4) * B_STRIDE + (c & 15) * 16;
    }

    auto issue_stage = [&](int slot, int kt) {      // kt in 64-k units
        uint32_t sbase = sb0 + slot * STAGE_BYTES;
        const unsigned char* srcA = gAb + (size_t)kt * 2 * ABLK_A;
        const unsigned char* srcB = gBb + (size_t)kt * 2 * ABLK_B;
#pragma unroll
        for (int i = 0; i < 4; i++) cp16(sbase + adst[i], srcA + (tid + i * 256) * 16);
#pragma unroll
        for (int i = 0; i < 4; i++) cp16(sbase + bdst[i], srcB + (tid + i * 256) * 16);
    };

    // ldmatrix lane addressing
    const int qrow = (lane & 7) + 8 * ((lane >> 3) & 1);
    const int kq   = (lane >> 4) * 8;

    float acc[2][8][4];
#pragma unroll
    for (int i = 0; i < 2; i++)
#pragma unroll
        for (int j = 0; j < 8; j++)
#pragma unroll
            for (int k = 0; k < 4; k++) acc[i][j][k] = 0.0f;

    // A fragments for one k16 half (ks in 0,16,32,48)
    auto ldA = [&](uint32_t sbase, int ks, uint32_t (&ah)[2][4]) {
#pragma unroll
        for (int m2 = 0; m2 < 2; m2++) {
            uint32_t ad = sbase + OFF_A + (wm * 32 + m2 * 16 + qrow) * A_STRIDE
                        + (ks + kq) * 2;
            ldm_x4(ah[m2], ad);
        }
    };

    // B loads + 16 MMAs for one k16 half
    auto halfK = [&](uint32_t sbase, int ks, const uint32_t (&ah)[2][4]) {
#pragma unroll
        for (int nc = 0; nc < 2; nc++) {
            uint32_t bh[2][4];
#pragma unroll
            for (int j = 0; j < 2; j++) {
                int n16 = nc * 2 + j;
                uint32_t bd = sbase + OFF_B + (ks + qrow) * B_STRIDE
                            + (wn * 64 + n16 * 16 + kq) * 2;
                ldm_x4_t(bh[j], bd);
            }
#pragma unroll
            for (int m2 = 0; m2 < 2; m2++)
#pragma unroll
                for (int j = 0; j < 2; j++)
#pragma unroll
                    for (int h = 0; h < 2; h++) {
                        int n8 = (nc * 2 + j) * 2 + h;
                        mma_f16(acc[m2][n8], ah[m2], bh[j][2*h], bh[j][2*h+1]);
                    }
        }
    };

    auto body = [&](int slot, int kt) {
        cp_wait<STAGES - 2>();
        __syncthreads();
        int nk = kt + STAGES - 1;
        if (nk < NK64) issue_stage((slot + STAGES - 1) % STAGES, nk);
        cp_commit();
        uint32_t sbase = sb0 + slot * STAGE_BYTES;
        uint32_t a0[2][4], a1[2][4];
        ldA(sbase, 0, a0);
        ldA(sbase, 16, a1);         // one-half-ahead A prefetch throughout
        halfK(sbase, 0, a0);
        ldA(sbase, 32, a0);
        halfK(sbase, 16, a1);
        ldA(sbase, 48, a1);
        halfK(sbase, 32, a0);
        halfK(sbase, 48, a1);
    };

    // ---- prologue: fill STAGES-1 slots ----
#pragma unroll
    for (int s = 0; s < STAGES - 1; s++) {
        issue_stage(s, s);
        cp_commit();
    }

    // ---- mainloop: 63 = 21 triples, +1 tail (63 mod 3 == 0) ----
#pragma unroll 1
    for (int kt = 0; kt < NK64 - 1; kt += 3) {
        body(0, kt);
        body(1, kt + 1);
        body(2, kt + 2);
    }
    body(0, NK64 - 1);

    // ---- epilogue ----
    const int crow0 = mt * BM + wm * 32 + (lane >> 2);
    const int ccol0 = nt * BN + wn * 64 + (lane & 3) * 2;
#pragma unroll
    for (int m2 = 0; m2 < 2; m2++) {
#pragma unroll
        for (int n8 = 0; n8 < 8; n8++) {
            int col = ccol0 + n8 * 8;
            float2 bv = *reinterpret_cast<const float2*>(bias + col);
            int r0 = crow0 + m2 * 16;
            float2 o0 = { acc[m2][n8][0] + bv.x, acc[m2][n8][1] + bv.y };
            float2 o1 = { acc[m2][n8][2] + bv.x, acc[m2][n8][3] + bv.y };
            *reinterpret_cast<float2*>(C + (size_t)r0 * SIZE_OUT + col) = o0;
            *reinterpret_cast<float2*>(C + (size_t)(r0 + 8) * SIZE_OUT + col) = o1;
        }
    }
}

extern "C" void kernel_launch(void* const* d_in, const int* in_sizes, int n_in,
                              void* d_out, int out_size) {
    const float* x    = (const float*)d_in[0];   // [8192, 4096]
    const float* w    = (const float*)d_in[1];   // [4096, 4096]
    const float* bias = (const float*)d_in[2];   // [4096]
    float* out = (float*)d_out;                  // [8192, 4096]

    cudaFuncSetAttribute(gemm_kernel, cudaFuncAttributeMaxDynamicSharedMemorySize,
                         SMEM_TOTAL);

    conv_a_kernel<<<(TOKENS * (SIZE_IN / 8)) / 256, 256>>>(x);
    conv_b_kernel<<<(SIZE_IN * (SIZE_OUT / 8)) / 256, 256>>>(w);
    gemm_kernel<<<(TOKENS / BM) * (SIZE_OUT / BN), THREADS, SMEM_TOTAL>>>(bias, out);
}